// round 2
// baseline (speedup 1.0000x reference)
#include <cuda_runtime.h>
#include <math.h>

// Compact per-edge scores staging: capacity 2^18 edges x 8 heads (8 MiB static).
#define MAX_E (1 << 18)
__device__ float g_scores[(size_t)MAX_E * 8];

// ---------------------------------------------------------------------------
// Kernel 1 (fused): claim + edge GEMM.
//   - lane 0 of each warp claims (u,v) in OUTPUT PLANE 0 via atomicMax(e+1).
//     (out was just memset to 0; the claimed int is later overwritten by the
//      winning edge's plane-0 score in the scatter kernel.)
//   - warp computes scores[e][0..7] = edge_attr[e] @ W + b, fully coalesced:
//     lane l loads float4 of dims [4l..4l+3] and its 32-float W slice.
// ---------------------------------------------------------------------------
__global__ void claim_gemm_kernel(const int* __restrict__ edge_index,
                                  const float* __restrict__ edge_attr,
                                  const float* __restrict__ W,
                                  const float* __restrict__ b,
                                  int* __restrict__ out_plane0,
                                  int E, int N) {
    int warp_id = (blockIdx.x * blockDim.x + threadIdx.x) >> 5;
    int lane = threadIdx.x & 31;
    if (warp_id >= E) return;
    const int e = warp_id;

    // --- claim (last edge id wins deterministically) ---
    if (lane == 0) {
        int u = edge_index[e];
        int v = edge_index[E + e];
        atomicMax(&out_plane0[(size_t)u * N + v], e + 1);
    }

    // --- W slice: rows lane*4 .. lane*4+3, 8 floats each = 8 float4 ---
    float4 w[8];
    const float4* Wv = reinterpret_cast<const float4*>(W) + lane * 8;
#pragma unroll
    for (int i = 0; i < 8; i++) w[i] = Wv[i];
    // w[2*d+0] = W[lane*4+d][0..3], w[2*d+1] = W[lane*4+d][4..7]

    // --- attr chunk (coalesced LDG.128 across warp) ---
    float4 a = reinterpret_cast<const float4*>(edge_attr + (size_t)e * 128)[lane];
    float av[4] = {a.x, a.y, a.z, a.w};

    float acc[8];
#pragma unroll
    for (int h = 0; h < 8; h++) acc[h] = 0.0f;
#pragma unroll
    for (int d = 0; d < 4; d++) {
        float4 lo = w[2 * d + 0];
        float4 hi = w[2 * d + 1];
        acc[0] += av[d] * lo.x;
        acc[1] += av[d] * lo.y;
        acc[2] += av[d] * lo.z;
        acc[3] += av[d] * lo.w;
        acc[4] += av[d] * hi.x;
        acc[5] += av[d] * hi.y;
        acc[6] += av[d] * hi.z;
        acc[7] += av[d] * hi.w;
    }

    // --- butterfly reduce across the 32 lanes ---
#pragma unroll
    for (int off = 16; off > 0; off >>= 1) {
#pragma unroll
        for (int h = 0; h < 8; h++)
            acc[h] += __shfl_xor_sync(0xFFFFFFFFu, acc[h], off);
    }

    // --- coalesced compact store ---
    if (lane < 8)
        g_scores[(size_t)e * 8 + lane] = acc[lane] + b[lane];
}

// ---------------------------------------------------------------------------
// Kernel 2: scatter. Winner check against plane 0, then 8 scattered stores.
// ---------------------------------------------------------------------------
__global__ void scatter_kernel(const int* __restrict__ edge_index,
                               float* __restrict__ out,
                               int E, int N) {
    int e = blockIdx.x * blockDim.x + threadIdx.x;
    if (e >= E) return;

    int u = edge_index[e];
    int v = edge_index[E + e];
    size_t cell = (size_t)u * N + v;

    int win = reinterpret_cast<const int*>(out)[cell];
    if (win != e + 1) return;

    float4 s0 = *reinterpret_cast<const float4*>(&g_scores[(size_t)e * 8]);
    float4 s1 = *reinterpret_cast<const float4*>(&g_scores[(size_t)e * 8 + 4]);

    size_t NN = (size_t)N * N;
    out[0 * NN + cell] = s0.x;   // overwrites the claim int with the real score
    out[1 * NN + cell] = s0.y;
    out[2 * NN + cell] = s0.z;
    out[3 * NN + cell] = s0.w;
    out[4 * NN + cell] = s1.x;
    out[5 * NN + cell] = s1.y;
    out[6 * NN + cell] = s1.z;
    out[7 * NN + cell] = s1.w;
}

// ---------------------------------------------------------------------------
// Launch. Inputs: edge_index[2,E] i32, edge_attr[E,128] f32, W[128,8] f32,
// b[8] f32, num_nodes (device scalar, ignored; N derived from out_size).
// ---------------------------------------------------------------------------
extern "C" void kernel_launch(void* const* d_in, const int* in_sizes, int n_in,
                              void* d_out, int out_size) {
    const int*   edge_index = (const int*)d_in[0];
    const float* edge_attr  = (const float*)d_in[1];
    const float* W          = (const float*)d_in[2];
    const float* b          = (const float*)d_in[3];
    float*       out        = (float*)d_out;

    int E = in_sizes[0] / 2;           // 131072
    int H = in_sizes[3];               // 8
    double nn = (double)out_size / (double)H;
    int N = (int)(sqrt(nn) + 0.5);     // 4096

    // 1) zero the full output (mandatory 512 MiB write).
    cudaMemsetAsync(out, 0, (size_t)out_size * sizeof(float), 0);

    // 2) fused claim (into plane 0) + coalesced warp-per-edge GEMM.
    {
        int threads = 256;                    // 8 warps/block
        int blocks = (E + 7) / 8;             // one warp per edge
        claim_gemm_kernel<<<blocks, threads>>>(edge_index, edge_attr, W, b,
                                               (int*)out, E, N);
    }

    // 3) winners scatter their 8 head scores.
    {
        int threads = 256;
        int blocks = (E + threads - 1) / threads;
        scatter_kernel<<<blocks, threads>>>(edge_index, out, E, N);
    }
}

// round 3
// speedup vs baseline: 1.8000x; 1.8000x over previous
#include <cuda_runtime.h>
#include <math.h>

// ---------------------------------------------------------------------------
// Kernel 1: claim — deterministic last-write-wins via atomicMax(e+1) into
// OUTPUT PLANE 0 (just zeroed). The winning edge later overwrites the id int
// with its real plane-0 score, so no separate winner buffer / memset needed.
// ---------------------------------------------------------------------------
__global__ __launch_bounds__(256)
void claim_kernel(const int* __restrict__ edge_index,
                  int* __restrict__ out_plane0, int E, int N) {
    int e = blockIdx.x * blockDim.x + threadIdx.x;
    if (e >= E) return;
    int u = edge_index[e];
    int v = edge_index[E + e];
    atomicMax(&out_plane0[(size_t)u * N + v], e + 1);
}

// ---------------------------------------------------------------------------
// Kernel 2 (fused): GEMM + scatter. 8 threads per edge.
//  - lane l loads float4s {l, l+8, l+16, l+24} of the row: each LDG.128 is
//    fully coalesced (8 lanes x 16B = 128B contiguous per group).
//  - W transposed in smem (sWt[h*128+d]): LDS banks = (4*lane+k) -> conflict
//    free, with 4-group broadcast across the warp.
//  - 3-step butterfly over the 8-lane segment, lane h stores head h:
//    exactly ONE scattered store per thread -> high MLP across 1M threads.
// ---------------------------------------------------------------------------
__global__ __launch_bounds__(256)
void gemm_scatter_kernel(const int* __restrict__ edge_index,
                         const float* __restrict__ edge_attr,
                         const float* __restrict__ W,
                         const float* __restrict__ b,
                         float* out, int E, int N) {
    __shared__ float sWt[8 * 128];
    __shared__ float sb[8];
    for (int i = threadIdx.x; i < 8 * 128; i += 256) {
        int h = i >> 7;
        int d = i & 127;
        sWt[i] = W[d * 8 + h];
    }
    if (threadIdx.x < 8) sb[threadIdx.x] = b[threadIdx.x];
    __syncthreads();

    int g    = threadIdx.x >> 3;   // group within block: 0..31
    int lane = threadIdx.x & 7;    // lane within 8-thread group
    int e = blockIdx.x * 32 + g;
    if (e >= E) return;            // E % 32 == 0 in practice -> warp-uniform

    int u = edge_index[e];
    int v = edge_index[E + e];
    size_t cell = (size_t)u * N + v;

    // Early winner read (overlaps with the GEMM below).
    int win = 0;
    if (lane == 0) win = *reinterpret_cast<const int*>(out + cell);
    win = __shfl_sync(0xFFFFFFFFu, win, 0, 8);

    // Partial dot products over this lane's 16 dims, all 8 heads.
    float acc[8];
#pragma unroll
    for (int h = 0; h < 8; h++) acc[h] = 0.0f;

    const float4* row = reinterpret_cast<const float4*>(edge_attr + (size_t)e * 128);
#pragma unroll
    for (int j = 0; j < 4; j++) {
        float4 a = row[lane + 8 * j];
        int d0 = 4 * (lane + 8 * j);
        float av[4] = {a.x, a.y, a.z, a.w};
#pragma unroll
        for (int k = 0; k < 4; k++) {
#pragma unroll
            for (int h = 0; h < 8; h++)
                acc[h] += av[k] * sWt[h * 128 + d0 + k];
        }
    }

    // Butterfly reduce across the 8-lane segment (all lanes end with full sums).
#pragma unroll
    for (int off = 4; off > 0; off >>= 1) {
#pragma unroll
        for (int h = 0; h < 8; h++)
            acc[h] += __shfl_xor_sync(0xFFFFFFFFu, acc[h], off, 8);
    }

    if (win != e + 1) return;      // a later duplicate edge owns this cell

    // lane h writes head h (static selection chain, no dynamic indexing).
    float val = acc[0] + sb[0];
#pragma unroll
    for (int h = 1; h < 8; h++)
        if (lane == h) val = acc[h] + sb[h];

    size_t NN = (size_t)N * N;
    out[(size_t)lane * NN + cell] = val;
}

// ---------------------------------------------------------------------------
// Launch. Inputs: edge_index[2,E] i32, edge_attr[E,128] f32, W[128,8] f32,
// b[8] f32, num_nodes (device scalar, ignored; N derived from out_size).
// ---------------------------------------------------------------------------
extern "C" void kernel_launch(void* const* d_in, const int* in_sizes, int n_in,
                              void* d_out, int out_size) {
    const int*   edge_index = (const int*)d_in[0];
    const float* edge_attr  = (const float*)d_in[1];
    const float* W          = (const float*)d_in[2];
    const float* b          = (const float*)d_in[3];
    float*       out        = (float*)d_out;

    int E = in_sizes[0] / 2;           // 131072
    int H = in_sizes[3];               // 8
    double nn = (double)out_size / (double)H;
    int N = (int)(sqrt(nn) + 0.5);     // 4096

    // 1) zero the output (mandatory 512 MiB write).
    cudaMemsetAsync(out, 0, (size_t)out_size * sizeof(float), 0);

    // 2) claim winners into plane 0.
    claim_kernel<<<(E + 255) / 256, 256>>>(edge_index, (int*)out, E, N);

    // 3) fused GEMM + scatter, 8 threads/edge.
    gemm_scatter_kernel<<<(E + 31) / 32, 256>>>(edge_index, edge_attr, W, b,
                                                out, E, N);
}